// round 13
// baseline (speedup 1.0000x reference)
#include <cuda_runtime.h>
#include <cuda_fp16.h>
#include <cstdint>

#define BB 4
#define SS 4096
#define DD 128
#define MTOT (BB*SS)

#define BM 64
#define BN 64

// Q scale: 1/sqrt(128) * log2(e)  (softmax uses ex2 directly)
#define QSCALE 0.12751743f

// fp16 scratch
__device__ __half g_qh[MTOT*DD];   // Q, pre-scaled by QSCALE
__device__ __half g_kh[MTOT*DD];   // K
__device__ __half g_vh[MTOT*DD];   // V
// split-segment merge scratch
__device__ float g_oacc[MTOT*DD];  // O partial accumulator (fp32)
__device__ float g_lacc[MTOT];     // l partial accumulator
__device__ int4  g_cnt4[64];       // 256 per-qtile completion counters

// ---------------------------------------------------------------------------
// helpers
// ---------------------------------------------------------------------------
__device__ __forceinline__ uint32_t smem_u32(const void* p) {
    uint32_t a;
    asm("{ .reg .u64 t; cvta.to.shared.u64 t, %1; cvt.u32.u64 %0, t; }"
        : "=r"(a) : "l"(p));
    return a;
}
__device__ __forceinline__ void cp16(uint32_t d, const void* s) {
    asm volatile("cp.async.cg.shared.global [%0], [%1], 16;" :: "r"(d), "l"(s));
}
#define CP_COMMIT() asm volatile("cp.async.commit_group;" ::: "memory")
#define CP_WAIT(N)  asm volatile("cp.async.wait_group %0;" :: "n"(N) : "memory")

__device__ __forceinline__ void ldsm4(uint32_t& r0, uint32_t& r1,
                                      uint32_t& r2, uint32_t& r3, uint32_t a) {
    asm volatile("ldmatrix.sync.aligned.m8n8.x4.shared.b16 {%0,%1,%2,%3},[%4];"
                 : "=r"(r0),"=r"(r1),"=r"(r2),"=r"(r3) : "r"(a));
}
__device__ __forceinline__ void ldsm4t(uint32_t& r0, uint32_t& r1,
                                       uint32_t& r2, uint32_t& r3, uint32_t a) {
    asm volatile("ldmatrix.sync.aligned.m8n8.x4.trans.shared.b16 {%0,%1,%2,%3},[%4];"
                 : "=r"(r0),"=r"(r1),"=r"(r2),"=r"(r3) : "r"(a));
}
__device__ __forceinline__ void mma16816(float* c, const uint32_t* a,
                                         uint32_t b0, uint32_t b1) {
    asm volatile("mma.sync.aligned.m16n8k16.row.col.f32.f16.f16.f32 "
                 "{%0,%1,%2,%3},{%4,%5,%6,%7},{%8,%9},{%0,%1,%2,%3};"
                 : "+f"(c[0]),"+f"(c[1]),"+f"(c[2]),"+f"(c[3])
                 : "r"(a[0]),"r"(a[1]),"r"(a[2]),"r"(a[3]),"r"(b0),"r"(b1));
}
__device__ __forceinline__ uint32_t packh2(float x, float y) {
    __half2 h = __floats2half2_rn(x, y);
    return *(uint32_t*)&h;
}
__device__ __forceinline__ float ex2f(float x) {
    float r;
    asm("ex2.approx.f32 %0, %1;" : "=f"(r) : "f"(x));
    return r;
}
__device__ __forceinline__ void split2(float a, float b, uint32_t& h, uint32_t& l) {
    __half ha = __float2half_rn(a), hb = __float2half_rn(b);
    __half la = __float2half_rn(a - __half2float(ha));
    __half lb = __float2half_rn(b - __half2float(hb));
    __half2 H = __halves2half2(ha, hb), L = __halves2half2(la, lb);
    h = *(uint32_t*)&H; l = *(uint32_t*)&L;
}
__device__ __forceinline__ void red2(float* p, float x, float y) {
    asm volatile("red.global.add.v2.f32 [%0], {%1,%2};" :: "l"(p), "f"(x), "f"(y)
                 : "memory");
}

// ---------------------------------------------------------------------------
// Kernel Z: zero the merge scratch (oacc + lacc + counters)
// ---------------------------------------------------------------------------
#define ZN_O (MTOT*DD/4)          // 524288 float4
#define ZN_L (MTOT/4)             // 4096 float4
#define ZN_T (ZN_O + ZN_L + 64)
__global__ __launch_bounds__(256) void zero_scratch(void)
{
    int i = blockIdx.x*256 + threadIdx.x;
    if (i >= ZN_T) return;
    float4 z = make_float4(0.f,0.f,0.f,0.f);
    if (i < ZN_O)            ((float4*)g_oacc)[i] = z;
    else if (i < ZN_O+ZN_L)  ((float4*)g_lacc)[i-ZN_O] = z;
    else                     g_cnt4[i-ZN_O-ZN_L] = make_int4(0,0,0,0);
}

// ---------------------------------------------------------------------------
// Kernel 1: QKV projection, 2-term split: y = (x_h + x_l) @ (fp16 W)^T.
// grid (256, 3), 128 threads. smem: xh 16K | xl 16K | wh 32K = 64KB.
// ---------------------------------------------------------------------------
#define PJ_XH 0
#define PJ_XL 16384
#define PJ_WH 32768
#define PJ_SMEM 65536

__global__ __launch_bounds__(128) void proj_mma(
    const float* __restrict__ x,
    const float* __restrict__ Wq,
    const float* __restrict__ Wk,
    const float* __restrict__ Wv)
{
    extern __shared__ char smem[];
    const uint32_t sb = smem_u32(smem);
    const int tid = threadIdx.x, wid = tid>>5, lane = tid&31;
    const int m0 = blockIdx.x * 64;
    const int psel = blockIdx.y;
    const float* W = (psel==0) ? Wq : (psel==1) ? Wk : Wv;

    for (int i = tid; i < 2048; i += 128) {
        int r = i>>4, c = i&15;
        const float* src = W + (size_t)r*DD + c*8;
        float4 v0 = *(const float4*)src;
        float4 v1 = *(const float4*)(src+4);
        uint4 h;
        h.x = packh2(v0.x, v0.y); h.y = packh2(v0.z, v0.w);
        h.z = packh2(v1.x, v1.y); h.w = packh2(v1.z, v1.w);
        uint32_t off = r*256 + ((c ^ (r&7))<<4);
        *(uint4*)(smem + PJ_WH + off) = h;
    }
    for (int i = tid; i < 1024; i += 128) {
        int r = i>>4, c = i&15;
        const float* src = x + (size_t)(m0+r)*DD + c*8;
        float4 v0 = *(const float4*)src;
        float4 v1 = *(const float4*)(src+4);
        uint4 hi, lo;
        split2(v0.x, v0.y, hi.x, lo.x);
        split2(v0.z, v0.w, hi.y, lo.y);
        split2(v1.x, v1.y, hi.z, lo.z);
        split2(v1.z, v1.w, hi.w, lo.w);
        uint32_t off = r*256 + ((c ^ (r&7))<<4);
        *(uint4*)(smem + PJ_XH + off) = hi;
        *(uint4*)(smem + PJ_XL + off) = lo;
    }
    __syncthreads();

    float acc[16][4];
#pragma unroll
    for (int n=0;n<16;++n){ acc[n][0]=acc[n][1]=acc[n][2]=acc[n][3]=0.f; }

    const int arow  = wid*16 + (lane&7) + (((lane>>3)&1)<<3);
    const int achnk = lane>>4;
    const int keyr  = (lane&7) + ((lane>>4)<<3);
    const int kchnk = (lane>>3)&1;

#pragma unroll
    for (int j=0;j<8;++j) {
        uint32_t ah[4], al[4];
        {
            uint32_t cc = 2*j + achnk;
            uint32_t off = arow*256 + ((cc ^ (arow&7))<<4);
            ldsm4(ah[0],ah[1],ah[2],ah[3], sb + PJ_XH + off);
            ldsm4(al[0],al[1],al[2],al[3], sb + PJ_XL + off);
        }
#pragma unroll
        for (int np=0;np<8;++np) {
            int key = np*16 + keyr;
            uint32_t cc = 2*j + kchnk;
            uint32_t off = key*256 + ((cc ^ (key&7))<<4);
            uint32_t b0,b1,b2,b3;
            ldsm4(b0,b1,b2,b3, sb + PJ_WH + off);
            mma16816(acc[2*np],   ah, b0, b1);
            mma16816(acc[2*np+1], ah, b2, b3);
            mma16816(acc[2*np],   al, b0, b1);
            mma16816(acc[2*np+1], al, b2, b3);
        }
    }

    const float sc = (psel==0) ? QSCALE : 1.0f;
    __half* outp = (psel==0) ? g_qh : (psel==1) ? g_kh : g_vh;
    const int g  = lane>>2;
    const int t2 = (lane&3)*2;
    __half* o0 = outp + (size_t)(m0 + wid*16 + g)*DD;
    __half* o1 = o0 + 8*DD;
#pragma unroll
    for (int nt=0; nt<16; ++nt) {
        *(uint32_t*)(o0 + nt*8 + t2) = packh2(acc[nt][0]*sc, acc[nt][1]*sc);
        *(uint32_t*)(o1 + nt*8 + t2) = packh2(acc[nt][2]*sc, acc[nt][3]*sc);
    }
}

// ---------------------------------------------------------------------------
// Kernel 2: fp16 flash attention, key-segmented with atomic merge.
// grid = 640: each (b, qt) split into ceil((qt+1)/16) segments of key tiles.
// 128 threads, register-resident Q, 3 CTAs/SM target.
// No-max softmax is linear over key partitions: partials just add.
// ---------------------------------------------------------------------------
#define SM_K 0
#define SM_V 32768
#define SM_TOTAL 65536

__global__ __launch_bounds__(128,3) void attn_mma(float* __restrict__ out)
{
    extern __shared__ char smem[];
    __shared__ int sflag;
    const uint32_t sb = smem_u32(smem);
    const int tid = threadIdx.x, wid = tid>>5, lane = tid&31;

    // ---- segment decode (longest q-tiles first) ----
    const int bid = blockIdx.x;
    const int b   = bid & 3;
    const int sid = 159 - (bid >> 2);
    int qt, seg, nseg;
    if (sid < 16)      { qt = sid;               seg = 0;      nseg = 1; }
    else if (sid < 48) { int t = sid-16; qt = 16 + (t>>1); seg = t&1;  nseg = 2; }
    else if (sid < 96) { int t = sid-48; qt = 32 + t/3;    seg = t%3;  nseg = 3; }
    else               { int t = sid-96; qt = 48 + (t>>2); seg = t&3;  nseg = 4; }
    const int ntl = qt + 1;
    const int k0 = seg*ntl/nseg;
    const int k1 = (seg+1)*ntl/nseg;
    const int n  = k1 - k0;
    const size_t qrow0 = (size_t)b*SS + (size_t)qt*BM;

    const int g  = lane >> 2;
    const int t2 = (lane & 3) * 2;

    // ---- Q fragments straight from gmem (register resident) ----
    uint32_t qa[8][4];
    {
        const __half* q0 = g_qh + (qrow0 + wid*16 + g)*DD;
#pragma unroll
        for (int j=0;j<8;++j) {
            qa[j][0] = *(const uint32_t*)(q0 + j*16 + t2);
            qa[j][1] = *(const uint32_t*)(q0 + 8*DD + j*16 + t2);
            qa[j][2] = *(const uint32_t*)(q0 + j*16 + t2 + 8);
            qa[j][3] = *(const uint32_t*)(q0 + 8*DD + j*16 + t2 + 8);
        }
    }

    const __half* kbase = g_kh + (size_t)b*SS*DD;
    const __half* vbase = g_vh + (size_t)b*SS*DD;

#pragma unroll 1
    for (int pre=0; pre<2; ++pre) {
        if (pre < n) {
            const __half* ks = kbase + (size_t)(k0+pre)*BN*DD;
            const __half* vs = vbase + (size_t)(k0+pre)*BN*DD;
            uint32_t kb = sb + SM_K + pre*16384;
            uint32_t vb = sb + SM_V + pre*16384;
            for (int i = tid; i < 1024; i += 128) {
                int r = i>>4, c = i&15;
                uint32_t off = r*256 + ((c ^ (r&7))<<4);
                cp16(kb + off, ks + r*DD + c*8);
                cp16(vb + off, vs + r*DD + c*8);
            }
            CP_COMMIT();
        }
    }

    float o[16][4];
#pragma unroll
    for (int d=0;d<16;++d){ o[d][0]=o[d][1]=o[d][2]=o[d][3]=0.f; }
    float lr0 = 0.f, lr1 = 0.f;

    const int keyr   = (lane&7) + ((lane>>4)<<3);
    const int kchunk = (lane>>3)&1;
    const int vrowr  = (lane&7) + (((lane>>3)&1)<<3);
    const int vchunk = lane>>4;

    for (int i = 0; i < n; ++i) {
        const int kt  = k0 + i;
        const int buf = i & 1;
        if (i + 2 <= n) { CP_WAIT(1); } else { CP_WAIT(0); }
        __syncthreads();

        const uint32_t kb = sb + SM_K + buf*16384;
        const uint32_t vb = sb + SM_V + buf*16384;

        // ---- S = Q K^T ----
        float s[8][4];
#pragma unroll
        for (int t=0;t<8;++t){ s[t][0]=s[t][1]=s[t][2]=s[t][3]=0.f; }
#pragma unroll
        for (int j=0;j<8;++j) {
#pragma unroll
            for (int tp=0;tp<4;++tp) {
                int key = tp*16 + keyr;
                int cc  = 2*j + kchunk;
                uint32_t addr = kb + key*256 + (((cc ^ (key&7)))<<4);
                uint32_t b0,b1,b2,b3;
                ldsm4(b0,b1,b2,b3, addr);
                mma16816(s[2*tp],   qa[j], b0, b1);
                mma16816(s[2*tp+1], qa[j], b2, b3);
            }
        }

        // ---- softmax: p = 2^s (Q pre-scaled by log2e) ----
        uint32_t pa[4][4];
        const bool diag = (kt == qt);
        const int r0l = wid*16 + g;
#pragma unroll
        for (int t=0;t<8;++t) {
            float v0 = s[t][0], v1 = s[t][1], v2 = s[t][2], v3 = s[t][3];
            if (diag) {
                int kc = t*8 + t2;
                if (kc   > r0l)   v0 = -1e30f;
                if (kc+1 > r0l)   v1 = -1e30f;
                if (kc   > r0l+8) v2 = -1e30f;
                if (kc+1 > r0l+8) v3 = -1e30f;
            }
            float p0 = ex2f(v0), p1 = ex2f(v1), p2 = ex2f(v2), p3 = ex2f(v3);
            lr0 += p0 + p1;
            lr1 += p2 + p3;
            if ((t & 1) == 0) {
                pa[t>>1][0] = packh2(p0,p1);
                pa[t>>1][1] = packh2(p2,p3);
            } else {
                pa[t>>1][2] = packh2(p0,p1);
                pa[t>>1][3] = packh2(p2,p3);
            }
        }

        // ---- O += P V ----
#pragma unroll
        for (int j=0;j<4;++j) {
#pragma unroll
            for (int dp=0;dp<8;++dp) {
                int row = j*16 + vrowr;
                int cc  = dp*2 + vchunk;
                uint32_t addr = vb + row*256 + (((cc ^ (row&7)))<<4);
                uint32_t v0,v1,v2,v3;
                ldsm4t(v0,v1,v2,v3, addr);
                mma16816(o[2*dp],   pa[j], v0, v1);
                mma16816(o[2*dp+1], pa[j], v2, v3);
            }
        }

        __syncthreads();
        if (i + 2 < n) {
            const __half* ks = kbase + (size_t)(kt+2)*BN*DD;
            const __half* vs = vbase + (size_t)(kt+2)*BN*DD;
            for (int ii = tid; ii < 1024; ii += 128) {
                int r = ii>>4, c = ii&15;
                uint32_t off = r*256 + ((c ^ (r&7))<<4);
                cp16(kb + off, ks + r*DD + c*8);
                cp16(vb + off, vs + r*DD + c*8);
            }
            CP_COMMIT();
        }
    }

    // ---- l reduction across quad ----
    lr0 += __shfl_xor_sync(0xffffffffu, lr0, 1);
    lr0 += __shfl_xor_sync(0xffffffffu, lr0, 2);
    lr1 += __shfl_xor_sync(0xffffffffu, lr1, 1);
    lr1 += __shfl_xor_sync(0xffffffffu, lr1, 2);

    const size_t row0 = qrow0 + wid*16 + g;   // rows row0, row0+8

    if (nseg == 1) {
        const float inv0 = 1.0f / lr0;
        const float inv1 = 1.0f / lr1;
        float* o0 = out + row0*DD;
        float* o1 = o0 + 8*DD;
#pragma unroll
        for (int dt=0;dt<16;++dt) {
            *(float2*)(o0 + dt*8 + t2) = make_float2(o[dt][0]*inv0, o[dt][1]*inv0);
            *(float2*)(o1 + dt*8 + t2) = make_float2(o[dt][2]*inv1, o[dt][3]*inv1);
        }
    } else {
        // ---- merge partials into gmem scratch ----
        float* p0 = g_oacc + row0*DD;
        float* p1 = p0 + 8*DD;
#pragma unroll
        for (int dt=0;dt<16;++dt) {
            red2(p0 + dt*8 + t2, o[dt][0], o[dt][1]);
            red2(p1 + dt*8 + t2, o[dt][2], o[dt][3]);
        }
        if ((lane&3)==0) {
            atomicAdd(&g_lacc[row0],     lr0);
            atomicAdd(&g_lacc[row0+8],   lr1);
        }
        __threadfence();
        if (tid == 0) {
            int* cnt = (int*)g_cnt4;
            sflag = (atomicAdd(&cnt[(b<<6)+qt], 1) == nseg-1);
        }
        __syncthreads();
        if (sflag) {
            __threadfence();
            const float inv0 = 1.0f / g_lacc[row0];
            const float inv1 = 1.0f / g_lacc[row0+8];
            const float* s0 = g_oacc + row0*DD;
            const float* s1 = s0 + 8*DD;
            float* o0 = out + row0*DD;
            float* o1 = o0 + 8*DD;
#pragma unroll
            for (int dt=0;dt<16;++dt) {
                float2 a = *(const float2*)(s0 + dt*8 + t2);
                float2 c = *(const float2*)(s1 + dt*8 + t2);
                *(float2*)(o0 + dt*8 + t2) = make_float2(a.x*inv0, a.y*inv0);
                *(float2*)(o1 + dt*8 + t2) = make_float2(c.x*inv1, c.y*inv1);
            }
        }
    }
}

// ---------------------------------------------------------------------------
extern "C" void kernel_launch(void* const* d_in, const int* in_sizes, int n_in,
                              void* d_out, int out_size)
{
    const float* x  = (const float*)d_in[0];
    const float* Wq = (const float*)d_in[1];
    const float* Wk = (const float*)d_in[2];
    const float* Wv = (const float*)d_in[3];
    float* out = (float*)d_out;

    cudaFuncSetAttribute(proj_mma,
                         cudaFuncAttributeMaxDynamicSharedMemorySize, PJ_SMEM);
    cudaFuncSetAttribute(attn_mma,
                         cudaFuncAttributeMaxDynamicSharedMemorySize, SM_TOTAL);

    zero_scratch<<<(ZN_T+255)/256, 256>>>();
    proj_mma<<<dim3(256,3), 128, PJ_SMEM>>>(x, Wq, Wk, Wv);
    attn_mma<<<640, 128, SM_TOTAL>>>(out);
}

// round 15
// speedup vs baseline: 1.1623x; 1.1623x over previous
#include <cuda_runtime.h>
#include <cuda_fp16.h>
#include <cstdint>

#define BB 4
#define SS 4096
#define DD 128
#define MTOT (BB*SS)

#define BM 64
#define BN 64

// Q scale: 1/sqrt(128) * log2(e)  (softmax uses ex2 directly)
#define QSCALE 0.12751743f

// fp16 scratch
__device__ __half g_qh[MTOT*DD];   // Q, pre-scaled by QSCALE
__device__ __half g_kh[MTOT*DD];   // K
__device__ __half g_vh[MTOT*DD];   // V
// per-segment merge slots (plain stores; only counters need zeroing)
__device__ float g_oacc[4][MTOT*DD];
__device__ float g_lacc[4][MTOT];
__device__ int   g_cnt[256];

// ---------------------------------------------------------------------------
// helpers
// ---------------------------------------------------------------------------
__device__ __forceinline__ uint32_t smem_u32(const void* p) {
    uint32_t a;
    asm("{ .reg .u64 t; cvta.to.shared.u64 t, %1; cvt.u32.u64 %0, t; }"
        : "=r"(a) : "l"(p));
    return a;
}
__device__ __forceinline__ void cp16(uint32_t d, const void* s) {
    asm volatile("cp.async.cg.shared.global [%0], [%1], 16;" :: "r"(d), "l"(s));
}
#define CP_COMMIT() asm volatile("cp.async.commit_group;" ::: "memory")
#define CP_WAIT(N)  asm volatile("cp.async.wait_group %0;" :: "n"(N) : "memory")

__device__ __forceinline__ void ldsm4(uint32_t& r0, uint32_t& r1,
                                      uint32_t& r2, uint32_t& r3, uint32_t a) {
    asm volatile("ldmatrix.sync.aligned.m8n8.x4.shared.b16 {%0,%1,%2,%3},[%4];"
                 : "=r"(r0),"=r"(r1),"=r"(r2),"=r"(r3) : "r"(a));
}
__device__ __forceinline__ void ldsm4t(uint32_t& r0, uint32_t& r1,
                                       uint32_t& r2, uint32_t& r3, uint32_t a) {
    asm volatile("ldmatrix.sync.aligned.m8n8.x4.trans.shared.b16 {%0,%1,%2,%3},[%4];"
                 : "=r"(r0),"=r"(r1),"=r"(r2),"=r"(r3) : "r"(a));
}
__device__ __forceinline__ void mma16816(float* c, const uint32_t* a,
                                         uint32_t b0, uint32_t b1) {
    asm volatile("mma.sync.aligned.m16n8k16.row.col.f32.f16.f16.f32 "
                 "{%0,%1,%2,%3},{%4,%5,%6,%7},{%8,%9},{%0,%1,%2,%3};"
                 : "+f"(c[0]),"+f"(c[1]),"+f"(c[2]),"+f"(c[3])
                 : "r"(a[0]),"r"(a[1]),"r"(a[2]),"r"(a[3]),"r"(b0),"r"(b1));
}
__device__ __forceinline__ uint32_t packh2(float x, float y) {
    __half2 h = __floats2half2_rn(x, y);
    return *(uint32_t*)&h;
}
__device__ __forceinline__ float ex2f(float x) {
    float r;
    asm("ex2.approx.f32 %0, %1;" : "=f"(r) : "f"(x));
    return r;
}
__device__ __forceinline__ void split2(float a, float b, uint32_t& h, uint32_t& l) {
    __half ha = __float2half_rn(a), hb = __float2half_rn(b);
    __half la = __float2half_rn(a - __half2float(ha));
    __half lb = __float2half_rn(b - __half2float(hb));
    __half2 H = __halves2half2(ha, hb), L = __halves2half2(la, lb);
    h = *(uint32_t*)&H; l = *(uint32_t*)&L;
}

// ---------------------------------------------------------------------------
// Kernel Z: zero the 256 completion counters (1 block)
// ---------------------------------------------------------------------------
__global__ void zero_cnt(void) { g_cnt[threadIdx.x] = 0; }

// ---------------------------------------------------------------------------
// Kernel 1: QKV projection, 2-term split: y = (x_h + x_l) @ (fp16 W)^T.
// grid (256, 3), 128 threads. smem: xh 16K | xl 16K | wh 32K = 64KB.
// ---------------------------------------------------------------------------
#define PJ_XH 0
#define PJ_XL 16384
#define PJ_WH 32768
#define PJ_SMEM 65536

__global__ __launch_bounds__(128) void proj_mma(
    const float* __restrict__ x,
    const float* __restrict__ Wq,
    const float* __restrict__ Wk,
    const float* __restrict__ Wv)
{
    extern __shared__ char smem[];
    const uint32_t sb = smem_u32(smem);
    const int tid = threadIdx.x, wid = tid>>5, lane = tid&31;
    const int m0 = blockIdx.x * 64;
    const int psel = blockIdx.y;
    const float* W = (psel==0) ? Wq : (psel==1) ? Wk : Wv;

    for (int i = tid; i < 2048; i += 128) {
        int r = i>>4, c = i&15;
        const float* src = W + (size_t)r*DD + c*8;
        float4 v0 = *(const float4*)src;
        float4 v1 = *(const float4*)(src+4);
        uint4 h;
        h.x = packh2(v0.x, v0.y); h.y = packh2(v0.z, v0.w);
        h.z = packh2(v1.x, v1.y); h.w = packh2(v1.z, v1.w);
        uint32_t off = r*256 + ((c ^ (r&7))<<4);
        *(uint4*)(smem + PJ_WH + off) = h;
    }
    for (int i = tid; i < 1024; i += 128) {
        int r = i>>4, c = i&15;
        const float* src = x + (size_t)(m0+r)*DD + c*8;
        float4 v0 = *(const float4*)src;
        float4 v1 = *(const float4*)(src+4);
        uint4 hi, lo;
        split2(v0.x, v0.y, hi.x, lo.x);
        split2(v0.z, v0.w, hi.y, lo.y);
        split2(v1.x, v1.y, hi.z, lo.z);
        split2(v1.z, v1.w, hi.w, lo.w);
        uint32_t off = r*256 + ((c ^ (r&7))<<4);
        *(uint4*)(smem + PJ_XH + off) = hi;
        *(uint4*)(smem + PJ_XL + off) = lo;
    }
    __syncthreads();

    float acc[16][4];
#pragma unroll
    for (int n=0;n<16;++n){ acc[n][0]=acc[n][1]=acc[n][2]=acc[n][3]=0.f; }

    const int arow  = wid*16 + (lane&7) + (((lane>>3)&1)<<3);
    const int achnk = lane>>4;
    const int keyr  = (lane&7) + ((lane>>4)<<3);
    const int kchnk = (lane>>3)&1;

#pragma unroll
    for (int j=0;j<8;++j) {
        uint32_t ah[4], al[4];
        {
            uint32_t cc = 2*j + achnk;
            uint32_t off = arow*256 + ((cc ^ (arow&7))<<4);
            ldsm4(ah[0],ah[1],ah[2],ah[3], sb + PJ_XH + off);
            ldsm4(al[0],al[1],al[2],al[3], sb + PJ_XL + off);
        }
#pragma unroll
        for (int np=0;np<8;++np) {
            int key = np*16 + keyr;
            uint32_t cc = 2*j + kchnk;
            uint32_t off = key*256 + ((cc ^ (key&7))<<4);
            uint32_t b0,b1,b2,b3;
            ldsm4(b0,b1,b2,b3, sb + PJ_WH + off);
            mma16816(acc[2*np],   ah, b0, b1);
            mma16816(acc[2*np+1], ah, b2, b3);
            mma16816(acc[2*np],   al, b0, b1);
            mma16816(acc[2*np+1], al, b2, b3);
        }
    }

    const float sc = (psel==0) ? QSCALE : 1.0f;
    __half* outp = (psel==0) ? g_qh : (psel==1) ? g_kh : g_vh;
    const int g  = lane>>2;
    const int t2 = (lane&3)*2;
    __half* o0 = outp + (size_t)(m0 + wid*16 + g)*DD;
    __half* o1 = o0 + 8*DD;
#pragma unroll
    for (int nt=0; nt<16; ++nt) {
        *(uint32_t*)(o0 + nt*8 + t2) = packh2(acc[nt][0]*sc, acc[nt][1]*sc);
        *(uint32_t*)(o1 + nt*8 + t2) = packh2(acc[nt][2]*sc, acc[nt][3]*sc);
    }
}

// ---------------------------------------------------------------------------
// Kernel 2: fp16 flash attention, key-segmented (<=4 segs of <=17 tiles),
// slot-based merge. 128 threads, register Q, 2 CTAs/SM (R12 core unchanged).
// ---------------------------------------------------------------------------
#define SM_K 0
#define SM_V 32768
#define SM_TOTAL 65536

__global__ __launch_bounds__(128,2) void attn_mma(float* __restrict__ out)
{
    extern __shared__ char smem[];
    __shared__ int sflag;
    const uint32_t sb = smem_u32(smem);
    const int tid = threadIdx.x, wid = tid>>5, lane = tid&31;

    // ---- segment decode (longest segments at low blockIdx) ----
    const int bid = blockIdx.x;
    const int b   = bid & 3;
    const int sid = 159 - (bid >> 2);
    int qt, seg, nseg;
    if (sid < 16)      { qt = sid;                seg = 0;     nseg = 1; }
    else if (sid < 48) { int t = sid-16; qt = 16 + (t>>1); seg = t&1;  nseg = 2; }
    else if (sid < 96) { int t = sid-48; qt = 32 + t/3;    seg = t%3;  nseg = 3; }
    else               { int t = sid-96; qt = 48 + (t>>2); seg = t&3;  nseg = 4; }
    const int ntl = qt + 1;
    const int k0 = seg*ntl/nseg;
    const int n  = (seg+1)*ntl/nseg - k0;
    const size_t qrow0 = (size_t)b*SS + (size_t)qt*BM;

    const int g  = lane >> 2;
    const int t2 = (lane & 3) * 2;

    // ---- Q fragments straight from gmem (register resident) ----
    uint32_t qa[8][4];
    {
        const __half* q0 = g_qh + (qrow0 + wid*16 + g)*DD;
#pragma unroll
        for (int j=0;j<8;++j) {
            qa[j][0] = *(const uint32_t*)(q0 + j*16 + t2);
            qa[j][1] = *(const uint32_t*)(q0 + 8*DD + j*16 + t2);
            qa[j][2] = *(const uint32_t*)(q0 + j*16 + t2 + 8);
            qa[j][3] = *(const uint32_t*)(q0 + 8*DD + j*16 + t2 + 8);
        }
    }

    const __half* kbase = g_kh + (size_t)b*SS*DD;
    const __half* vbase = g_vh + (size_t)b*SS*DD;

#pragma unroll 1
    for (int pre=0; pre<2; ++pre) {
        if (pre < n) {
            const __half* ks = kbase + (size_t)(k0+pre)*BN*DD;
            const __half* vs = vbase + (size_t)(k0+pre)*BN*DD;
            uint32_t kb = sb + SM_K + pre*16384;
            uint32_t vb = sb + SM_V + pre*16384;
            for (int i = tid; i < 1024; i += 128) {
                int r = i>>4, c = i&15;
                uint32_t off = r*256 + ((c ^ (r&7))<<4);
                cp16(kb + off, ks + r*DD + c*8);
                cp16(vb + off, vs + r*DD + c*8);
            }
            CP_COMMIT();
        }
    }

    float o[16][4];
#pragma unroll
    for (int d=0;d<16;++d){ o[d][0]=o[d][1]=o[d][2]=o[d][3]=0.f; }
    float lr0 = 0.f, lr1 = 0.f;

    const int keyr   = (lane&7) + ((lane>>4)<<3);
    const int kchunk = (lane>>3)&1;
    const int vrowr  = (lane&7) + (((lane>>3)&1)<<3);
    const int vchunk = lane>>4;

    for (int i = 0; i < n; ++i) {
        const int kt  = k0 + i;
        const int buf = i & 1;
        if (i + 2 <= n) { CP_WAIT(1); } else { CP_WAIT(0); }
        __syncthreads();

        const uint32_t kb = sb + SM_K + buf*16384;
        const uint32_t vb = sb + SM_V + buf*16384;

        // ---- S = Q K^T ----
        float s[8][4];
#pragma unroll
        for (int t=0;t<8;++t){ s[t][0]=s[t][1]=s[t][2]=s[t][3]=0.f; }
#pragma unroll
        for (int j=0;j<8;++j) {
#pragma unroll
            for (int tp=0;tp<4;++tp) {
                int key = tp*16 + keyr;
                int cc  = 2*j + kchunk;
                uint32_t addr = kb + key*256 + (((cc ^ (key&7)))<<4);
                uint32_t b0,b1,b2,b3;
                ldsm4(b0,b1,b2,b3, addr);
                mma16816(s[2*tp],   qa[j], b0, b1);
                mma16816(s[2*tp+1], qa[j], b2, b3);
            }
        }

        // ---- softmax: p = 2^s (Q pre-scaled by log2e) ----
        uint32_t pa[4][4];
        const bool diag = (kt == qt);
        const int r0l = wid*16 + g;
#pragma unroll
        for (int t=0;t<8;++t) {
            float v0 = s[t][0], v1 = s[t][1], v2 = s[t][2], v3 = s[t][3];
            if (diag) {
                int kc = t*8 + t2;
                if (kc   > r0l)   v0 = -1e30f;
                if (kc+1 > r0l)   v1 = -1e30f;
                if (kc   > r0l+8) v2 = -1e30f;
                if (kc+1 > r0l+8) v3 = -1e30f;
            }
            float p0 = ex2f(v0), p1 = ex2f(v1), p2 = ex2f(v2), p3 = ex2f(v3);
            lr0 += p0 + p1;
            lr1 += p2 + p3;
            if ((t & 1) == 0) {
                pa[t>>1][0] = packh2(p0,p1);
                pa[t>>1][1] = packh2(p2,p3);
            } else {
                pa[t>>1][2] = packh2(p0,p1);
                pa[t>>1][3] = packh2(p2,p3);
            }
        }

        // ---- O += P V ----
#pragma unroll
        for (int j=0;j<4;++j) {
#pragma unroll
            for (int dp=0;dp<8;++dp) {
                int row = j*16 + vrowr;
                int cc  = dp*2 + vchunk;
                uint32_t addr = vb + row*256 + (((cc ^ (row&7)))<<4);
                uint32_t v0,v1,v2,v3;
                ldsm4t(v0,v1,v2,v3, addr);
                mma16816(o[2*dp],   pa[j], v0, v1);
                mma16816(o[2*dp+1], pa[j], v2, v3);
            }
        }

        __syncthreads();
        if (i + 2 < n) {
            const __half* ks = kbase + (size_t)(kt+2)*BN*DD;
            const __half* vs = vbase + (size_t)(kt+2)*BN*DD;
            for (int ii = tid; ii < 1024; ii += 128) {
                int r = ii>>4, c = ii&15;
                uint32_t off = r*256 + ((c ^ (r&7))<<4);
                cp16(kb + off, ks + r*DD + c*8);
                cp16(vb + off, vs + r*DD + c*8);
            }
            CP_COMMIT();
        }
    }

    // ---- l reduction across quad ----
    lr0 += __shfl_xor_sync(0xffffffffu, lr0, 1);
    lr0 += __shfl_xor_sync(0xffffffffu, lr0, 2);
    lr1 += __shfl_xor_sync(0xffffffffu, lr1, 1);
    lr1 += __shfl_xor_sync(0xffffffffu, lr1, 2);

    const size_t row0 = qrow0 + wid*16 + g;   // rows row0, row0+8

    if (nseg == 1) {
        const float inv0 = 1.0f / lr0;
        const float inv1 = 1.0f / lr1;
        float* o0 = out + row0*DD;
        float* o1 = o0 + 8*DD;
#pragma unroll
        for (int dt=0;dt<16;++dt) {
            *(float2*)(o0 + dt*8 + t2) = make_float2(o[dt][0]*inv0, o[dt][1]*inv0);
            *(float2*)(o1 + dt*8 + t2) = make_float2(o[dt][2]*inv1, o[dt][3]*inv1);
        }
    } else {
        // ---- store partial (plain stores into this segment's slot) ----
        float* p0 = g_oacc[seg] + row0*DD;
        float* p1 = p0 + 8*DD;
#pragma unroll
        for (int dt=0;dt<16;++dt) {
            *(float2*)(p0 + dt*8 + t2) = make_float2(o[dt][0], o[dt][1]);
            *(float2*)(p1 + dt*8 + t2) = make_float2(o[dt][2], o[dt][3]);
        }
        if ((lane&3)==0) {
            g_lacc[seg][row0]   = lr0;
            g_lacc[seg][row0+8] = lr1;
        }
        __threadfence();
        if (tid == 0)
            sflag = (atomicAdd(&g_cnt[(b<<6)+qt], 1) == nseg-1);
        __syncthreads();
        if (sflag) {
            __threadfence();
            float l0 = 0.f, l1 = 0.f;
            for (int sgi = 0; sgi < nseg; ++sgi) {
                l0 += g_lacc[sgi][row0];
                l1 += g_lacc[sgi][row0+8];
            }
            const float inv0 = 1.0f / l0;
            const float inv1 = 1.0f / l1;
            float* o0 = out + row0*DD;
            float* o1 = o0 + 8*DD;
#pragma unroll
            for (int dt=0;dt<16;++dt) {
                float2 a = make_float2(0.f,0.f), c = make_float2(0.f,0.f);
                for (int sgi = 0; sgi < nseg; ++sgi) {
                    float2 av = *(const float2*)(g_oacc[sgi] + row0*DD + dt*8 + t2);
                    float2 cv = *(const float2*)(g_oacc[sgi] + (row0+8)*DD + dt*8 + t2);
                    a.x += av.x; a.y += av.y;
                    c.x += cv.x; c.y += cv.y;
                }
                *(float2*)(o0 + dt*8 + t2) = make_float2(a.x*inv0, a.y*inv0);
                *(float2*)(o1 + dt*8 + t2) = make_float2(c.x*inv1, c.y*inv1);
            }
        }
    }
}

// ---------------------------------------------------------------------------
extern "C" void kernel_launch(void* const* d_in, const int* in_sizes, int n_in,
                              void* d_out, int out_size)
{
    const float* x  = (const float*)d_in[0];
    const float* Wq = (const float*)d_in[1];
    const float* Wk = (const float*)d_in[2];
    const float* Wv = (const float*)d_in[3];
    float* out = (float*)d_out;

    cudaFuncSetAttribute(proj_mma,
                         cudaFuncAttributeMaxDynamicSharedMemorySize, PJ_SMEM);
    cudaFuncSetAttribute(attn_mma,
                         cudaFuncAttributeMaxDynamicSharedMemorySize, SM_TOTAL);

    zero_cnt<<<1, 256>>>();
    proj_mma<<<dim3(256,3), 128, PJ_SMEM>>>(x, Wq, Wk, Wv);
    attn_mma<<<640, 128, SM_TOTAL>>>(out);
}